// round 13
// baseline (speedup 1.0000x reference)
#include <cuda_runtime.h>

#define NMID 60
#define NT 256      // threads/block
#define SLOTS 8     // warp-slots per warp (8 rows each) -> 512 rows/block

// Collapsed affine map: out = x @ M + c. Ready-flag orders build -> consume.
__device__ float g_M[16 * 4];
__device__ float g_c[4];
__device__ unsigned g_ready = 0;

// ---------------------------------------------------------------------------
// Kernel A: fold the 62-layer affine chain into (M, c), depth-6 tree in smem.
// Triggers PDL completion IMMEDIATELY; ordering is via g_ready.
// ---------------------------------------------------------------------------
__global__ __launch_bounds__(512) void build_composite(
    const float* __restrict__ W1, const float* __restrict__ b1,
    const float* __restrict__ Ws, const float* __restrict__ bs,
    const float* __restrict__ W2, const float* __restrict__ b2) {
#if __CUDA_ARCH__ >= 900
    cudaTriggerProgrammaticLaunchCompletion();   // release secondary NOW
#endif
    __shared__ float Wb[2][NMID * 64];
    __shared__ float bb[2][NMID * 8];
    __shared__ float A1[8 * 16];
    __shared__ float v1[8];

    const int tid = threadIdx.x;  // 0..511

    {
        const float4* W4 = (const float4*)Ws;
        float4* dW = (float4*)&Wb[0][0];
        for (int i = tid; i < NMID * 16; i += 512) dW[i] = W4[i];
        const float4* b4 = (const float4*)bs;
        float4* db = (float4*)&bb[0][0];
        if (tid < NMID * 2) db[tid] = b4[tid];
    }
    __syncthreads();

    int cur = 0, cnt = NMID;
    while (cnt > 1) {
        const int half = cnt >> 1;
        const int nxt = cur ^ 1;

        for (int idx = tid; idx < half * 64; idx += 512) {
            const int p = idx >> 6, e = idx & 63, i = e >> 3, j = e & 7;
            const float* A = &Wb[cur][(2 * p + 1) * 64];
            const float* B = &Wb[cur][(2 * p) * 64];
            float acc = 0.0f;
#pragma unroll
            for (int k = 0; k < 8; ++k) acc += A[i * 8 + k] * B[k * 8 + j];
            Wb[nxt][p * 64 + e] = acc;
        }
        for (int idx = tid; idx < half * 8; idx += 512) {
            const int p = idx >> 3, i = idx & 7;
            const float* A = &Wb[cur][(2 * p + 1) * 64];
            const float* bB = &bb[cur][(2 * p) * 8];
            const float* bA = &bb[cur][(2 * p + 1) * 8];
            float acc = bA[i];
#pragma unroll
            for (int k = 0; k < 8; ++k) acc += A[i * 8 + k] * bB[k];
            bb[nxt][p * 8 + i] = acc;
        }
        if (cnt & 1) {
            for (int idx = tid; idx < 64; idx += 512)
                Wb[nxt][half * 64 + idx] = Wb[cur][(cnt - 1) * 64 + idx];
            if (tid < 8) bb[nxt][half * 8 + tid] = bb[cur][(cnt - 1) * 8 + tid];
        }
        __syncthreads();
        cnt = half + (cnt & 1);
        cur = nxt;
    }

    const float* T = &Wb[cur][0];
    const float* bchain = &bb[cur][0];
    for (int idx = tid; idx < 128; idx += 512) {
        const int k = idx >> 4, i = idx & 15;
        float acc = 0.0f;
#pragma unroll
        for (int j = 0; j < 8; ++j) acc += T[k * 8 + j] * W1[j * 16 + i];
        A1[k * 16 + i] = acc;
    }
    if (tid < 8) {
        float acc = bchain[tid];
#pragma unroll
        for (int j = 0; j < 8; ++j) acc += T[tid * 8 + j] * b1[j];
        v1[tid] = acc;
    }
    __syncthreads();

    if (tid < 64) {
        const int i = tid >> 2, o = tid & 3;
        float acc = 0.0f;
#pragma unroll
        for (int k = 0; k < 8; ++k) acc += W2[o * 8 + k] * A1[k * 16 + i];
        g_M[tid] = acc;
    }
    if (tid < 4) {
        float acc = b2[tid];
#pragma unroll
        for (int k = 0; k < 8; ++k) acc += W2[tid * 8 + k] * v1[k];
        g_c[tid] = acc;
    }
    __syncthreads();

    if (tid == 0) {
        asm volatile("st.release.gpu.b32 [%0], %1;"
                     :: "l"(&g_ready), "r"(1u) : "memory");
    }
}

// ---------------------------------------------------------------------------
// Kernel B: fully-coalesced streaming GEMV.
// 4 lanes cooperate per row: lane t loads float4 idx gslot*32+t (512B/instr,
// 4 lines/instr -> 4x fewer L1 wavefronts than row-per-thread). Lane quarter
// q=t&3 keeps its 16 M entries in registers; 2 shfl.bfly rounds reduce the
// 4 partials; lane q==0 adds c and stores. Zero LDS in the hot loop.
// ---------------------------------------------------------------------------
__global__ __launch_bounds__(NT) void apply_affine(
    const float4* __restrict__ x4, float4* __restrict__ y4, int n_rows) {
    const int tid = threadIdx.x;
    const int lane = tid & 31;
    const int warp = tid >> 5;
    const int q = lane & 3;               // quarter within row

    // Base warp-slot for this warp: block covers 64 slots (512 rows).
    const int gslot0 = blockIdx.x * 64 + warp * SLOTS;
    const long n4 = (long)n_rows * 4;     // total float4 in x

    // ---- Front-batch 8 fully-coalesced LDG.128 (independent of build) ----
    float4 xb[SLOTS];
#pragma unroll
    for (int s = 0; s < SLOTS; ++s) {
        const long idx = (long)(gslot0 + s) * 32 + lane;
        if (idx < n4) xb[s] = __ldcs(&x4[idx]);
        else xb[s] = make_float4(0.f, 0.f, 0.f, 0.f);
    }

    // ---- Wait for build's (M, c) ----
    if (tid == 0) {
        unsigned v;
        asm volatile("ld.acquire.gpu.b32 %0, [%1];"
                     : "=r"(v) : "l"(&g_ready) : "memory");
        while (v == 0) {
            __nanosleep(64);
            asm volatile("ld.acquire.gpu.b32 %0, [%1];"
                         : "=r"(v) : "l"(&g_ready) : "memory");
        }
    }
    __syncthreads();

    // Per-lane M slice: inputs 4q..4q+3 -> m[i*4+o] = M[(4q+i)*4+o],
    // contiguous 16 floats at g_M[16q]. One-time broadcast loads.
    float m[16];
    {
        const float4* M4 = (const float4*)g_M;
#pragma unroll
        for (int j = 0; j < 4; ++j) {
            const float4 t4 = M4[q * 4 + j];
            m[j * 4 + 0] = t4.x; m[j * 4 + 1] = t4.y;
            m[j * 4 + 2] = t4.z; m[j * 4 + 3] = t4.w;
        }
    }
    const float4 cbias = *(const float4*)g_c;

    // ---- Hot loop: one slot = 8 rows per warp ----
#pragma unroll
    for (int s = 0; s < SLOTS; ++s) {
        const float4 v = xb[s];
        float p0, p1, p2, p3;
        p0 = v.x * m[0];  p1 = v.x * m[1];  p2 = v.x * m[2];  p3 = v.x * m[3];
        p0 = fmaf(v.y, m[4],  p0); p1 = fmaf(v.y, m[5],  p1);
        p2 = fmaf(v.y, m[6],  p2); p3 = fmaf(v.y, m[7],  p3);
        p0 = fmaf(v.z, m[8],  p0); p1 = fmaf(v.z, m[9],  p1);
        p2 = fmaf(v.z, m[10], p2); p3 = fmaf(v.z, m[11], p3);
        p0 = fmaf(v.w, m[12], p0); p1 = fmaf(v.w, m[13], p1);
        p2 = fmaf(v.w, m[14], p2); p3 = fmaf(v.w, m[15], p3);

        // Reduce across the 4-lane group (bfly masks 1, 2).
        p0 += __shfl_xor_sync(0xffffffffu, p0, 1);
        p1 += __shfl_xor_sync(0xffffffffu, p1, 1);
        p2 += __shfl_xor_sync(0xffffffffu, p2, 1);
        p3 += __shfl_xor_sync(0xffffffffu, p3, 1);
        p0 += __shfl_xor_sync(0xffffffffu, p0, 2);
        p1 += __shfl_xor_sync(0xffffffffu, p1, 2);
        p2 += __shfl_xor_sync(0xffffffffu, p2, 2);
        p3 += __shfl_xor_sync(0xffffffffu, p3, 2);

        if (q == 0) {
            const int row = (gslot0 + s) * 8 + (lane >> 2);
            if (row < n_rows)
                __stcs(&y4[row], make_float4(p0 + cbias.x, p1 + cbias.y,
                                             p2 + cbias.z, p3 + cbias.w));
        }
    }
}

// ---------------------------------------------------------------------------
// Launch: build (PDL-triggers at start), then apply overlapped via PDL.
// ---------------------------------------------------------------------------
extern "C" void kernel_launch(void* const* d_in, const int* in_sizes, int n_in,
                              void* d_out, int out_size) {
    const float* x  = (const float*)d_in[0];   // [B,16]
    const float* W1 = (const float*)d_in[1];   // [8,16]
    const float* b1 = (const float*)d_in[2];   // [8]
    const float* Ws = (const float*)d_in[3];   // [60,8,8]
    const float* bs = (const float*)d_in[4];   // [60,8]
    const float* W2 = (const float*)d_in[5];   // [4,8]
    const float* b2 = (const float*)d_in[6];   // [4]
    float* out = (float*)d_out;                // [B,4]

    const int n_rows = in_sizes[0] / 16;       // 4194304

    build_composite<<<1, 512>>>(W1, b1, Ws, bs, W2, b2);

    const int rows_per_block = NT * 2;         // 512 rows (64 slots of 8)
    const int blocks = (n_rows + rows_per_block - 1) / rows_per_block;

    cudaLaunchConfig_t cfg = {};
    cfg.gridDim = dim3(blocks);
    cfg.blockDim = dim3(NT);
    cfg.dynamicSmemBytes = 0;
    cfg.stream = 0;
    cudaLaunchAttribute attrs[1];
    attrs[0].id = cudaLaunchAttributeProgrammaticStreamSerialization;
    attrs[0].val.programmaticStreamSerializationAllowed = 1;
    cfg.attrs = attrs;
    cfg.numAttrs = 1;

    cudaError_t err = cudaLaunchKernelEx(&cfg, apply_affine,
                                         (const float4*)x, (float4*)out, n_rows);
    if (err != cudaSuccess) {
        apply_affine<<<blocks, NT>>>((const float4*)x, (float4*)out, n_rows);
    }
}